// round 14
// baseline (speedup 1.0000x reference)
#include <cuda_runtime.h>
#include <cuda_fp16.h>

#define BB_  2
#define SS_  2048
#define DD_  1024
#define HH_  16
#define HDIM 64

// Scratch
__device__ __align__(16) __half g_Q[(size_t)BB_ * HH_ * SS_ * HDIM];
__device__ __align__(16) __half g_K[(size_t)BB_ * HH_ * SS_ * HDIM];
__device__ __align__(16) __half g_V[(size_t)BB_ * HH_ * SS_ * HDIM];
__device__ __align__(16) __half g_Xh[(size_t)3 * BB_ * SS_ * DD_];
__device__ __align__(16) __half g_Wh[(size_t)3 * DD_ * DD_];
__device__ unsigned int g_mb[(size_t)BB_ * SS_ * SS_ / 32];

#define QSCALE 0.1803368801111204f   // 0.125 * log2(e)
#define NEGH2  0xFBFFFBFFu           // half2(-65504, -65504)
#define ONESH2 0x3C003C00u

// ---------------------------------------------------------------------------
__device__ __forceinline__ void mma16816(float (&c)[4], const unsigned (&a)[4],
                                         const unsigned (&b)[2]) {
    asm volatile(
        "mma.sync.aligned.m16n8k16.row.col.f32.f16.f16.f32 "
        "{%0,%1,%2,%3}, {%4,%5,%6,%7}, {%8,%9}, {%0,%1,%2,%3};\n"
        : "+f"(c[0]), "+f"(c[1]), "+f"(c[2]), "+f"(c[3])
        : "r"(a[0]), "r"(a[1]), "r"(a[2]), "r"(a[3]), "r"(b[0]), "r"(b[1]));
}
__device__ __forceinline__ void mma16816_h(unsigned (&c)[2], const unsigned (&a)[4],
                                           const unsigned (&b)[2]) {
    asm volatile(
        "mma.sync.aligned.m16n8k16.row.col.f16.f16.f16.f16 "
        "{%0,%1}, {%2,%3,%4,%5}, {%6,%7}, {%0,%1};\n"
        : "+r"(c[0]), "+r"(c[1])
        : "r"(a[0]), "r"(a[1]), "r"(a[2]), "r"(a[3]), "r"(b[0]), "r"(b[1]));
}

__device__ __forceinline__ unsigned pack_h2(float lo, float hi) {
    __half2 h = __floats2half2_rn(lo, hi);
    return *reinterpret_cast<unsigned*>(&h);
}
__device__ __forceinline__ unsigned ex2_h2(unsigned a) {
    unsigned d;
    asm("ex2.approx.f16x2 %0, %1;" : "=r"(d) : "r"(a));
    return d;
}
__device__ __forceinline__ unsigned smem_u32(const void* p) {
    unsigned r;
    asm("{ .reg .u64 t; cvta.to.shared.u64 t, %1; cvt.u32.u64 %0, t; }"
        : "=r"(r) : "l"(p));
    return r;
}

#define CP_ASYNC16(dst, src) \
    asm volatile("cp.async.cg.shared.global [%0], [%1], 16;\n" ::"r"(dst), "l"(src))
#define CP_COMMIT() asm volatile("cp.async.commit_group;\n")
#define CP_WAIT(n)  asm volatile("cp.async.wait_group %0;\n" ::"n"(n))

__device__ __forceinline__ void ldsm_x4(unsigned& r0, unsigned& r1, unsigned& r2,
                                        unsigned& r3, unsigned addr) {
    asm volatile("ldmatrix.sync.aligned.m8n8.x4.shared.b16 {%0,%1,%2,%3}, [%4];"
                 : "=r"(r0), "=r"(r1), "=r"(r2), "=r"(r3) : "r"(addr));
}
__device__ __forceinline__ void ldsm_x4_t(unsigned& r0, unsigned& r1, unsigned& r2,
                                          unsigned& r3, unsigned addr) {
    asm volatile("ldmatrix.sync.aligned.m8n8.x4.trans.shared.b16 {%0,%1,%2,%3}, [%4];"
                 : "=r"(r0), "=r"(r1), "=r"(r2), "=r"(r3) : "r"(addr));
}

// ---------------------------------------------------------------------------
// mask pack (side stream): 8 elems/thread, 4096 blocks.
// ---------------------------------------------------------------------------
__global__ void pack_mask_kernel(const int4* __restrict__ mask) {
    int tid = threadIdx.x;
    int j = blockIdx.x * 256 + tid;             // 8-element group index
    int4 m0 = mask[2 * j];
    int4 m1 = mask[2 * j + 1];
    unsigned n0 = (unsigned)(m0.x != 0) | ((unsigned)(m0.y != 0) << 1) |
                  ((unsigned)(m0.z != 0) << 2) | ((unsigned)(m0.w != 0) << 3);
    unsigned n1 = (unsigned)(m1.x != 0) | ((unsigned)(m1.y != 0) << 1) |
                  ((unsigned)(m1.z != 0) << 2) | ((unsigned)(m1.w != 0) << 3);
    unsigned byte = n0 | (n1 << 4);
    unsigned v = byte << ((tid & 3) * 8);
    v |= __shfl_xor_sync(0xffffffffu, v, 1);
    v |= __shfl_xor_sync(0xffffffffu, v, 2);
    if ((tid & 3) == 0) g_mb[j >> 2] = v;
}

// ---------------------------------------------------------------------------
// X/W fp32 -> fp16 converts (main stream, feeds proj): 2x MLP.
// blocks [0,6144): X (3 tensors x 2048); [6144,7680): W (3 x 512).
// ---------------------------------------------------------------------------
#define CONV_X_BLKS 6144
#define CONV_BLKS   7680

__global__ void conv_kernel(const float4* __restrict__ xq,
                            const float4* __restrict__ xk,
                            const float4* __restrict__ xv,
                            const float4* __restrict__ wq,
                            const float4* __restrict__ wk,
                            const float4* __restrict__ wv) {
    int b = blockIdx.x;
    int tid = threadIdx.x;
    if (b < CONV_X_BLKS) {
        int z = b / 2048;
        const float4* src = (z == 0) ? xq : (z == 1) ? xk : xv;
        uint2* dst = (uint2*)g_Xh + (size_t)z * (BB_ * SS_ * DD_ / 4);
        int i = (b - z * 2048) * 512 + tid;
        float4 v0 = src[i];
        float4 v1 = src[i + 256];
        dst[i] = make_uint2(pack_h2(v0.x, v0.y), pack_h2(v0.z, v0.w));
        dst[i + 256] = make_uint2(pack_h2(v1.x, v1.y), pack_h2(v1.z, v1.w));
    } else {
        int j = b - CONV_X_BLKS;
        int z = j >> 9;
        const float4* src = (z == 0) ? wq : (z == 1) ? wk : wv;
        uint2* dst = (uint2*)g_Wh + (size_t)z * (DD_ * DD_ / 4);
        int i = (j & 511) * 512 + tid;
        float4 v0 = src[i];
        float4 v1 = src[i + 256];
        dst[i] = make_uint2(pack_h2(v0.x, v0.y), pack_h2(v0.z, v0.w));
        dst[i + 256] = make_uint2(pack_h2(v1.x, v1.y), pack_h2(v1.z, v1.w));
    }
}

// ---------------------------------------------------------------------------
// fused projection GEMMs (z=0/1/2 -> Q/K/V), fp16 datapath.
// 128x64 tiles, 128 threads (4 warps, 64x32 each), 3-stage cp.async,
// one barrier per k-step, occupancy 3.
// ---------------------------------------------------------------------------
#define PSTG_A 8192          // halfs per A stage (128 x 64)
#define PSTG_B 4096          // halfs per B stage (64 x 64)

__global__ __launch_bounds__(128, 3) void proj_kernel(const float* __restrict__ bqp,
                                                      const float* __restrict__ bkp,
                                                      const float* __restrict__ bvp) {
    extern __shared__ __half smemh[];
    __half* sA = smemh;                 // [3][8192]
    __half* sB = smemh + 3 * PSTG_A;    // [3][4096]

    const int z = blockIdx.z;
    const __half* X = g_Xh + (size_t)z * BB_ * SS_ * DD_;
    const __half* W = g_Wh + (size_t)z * DD_ * DD_;
    __half* out = (z == 0) ? g_Q : (z == 1) ? g_K : g_V;
    const float* bias = (z == 0) ? bqp : (z == 1) ? bkp : bvp;

    const int tid = threadIdx.x;
    const int warp = tid >> 5, lane = tid & 31;
    const int g = lane >> 2, t = lane & 3;
    const int wm = warp & 1, wn = warp >> 1;
    const int m0 = blockIdx.y * 128, n0 = blockIdx.x * 64;

    const unsigned sAu = smem_u32(sA), sBu = smem_u32(sB);

    auto load_stage = [&](int buf, int kk) {
#pragma unroll
        for (int i = 0; i < 8; i++) {
            int id = tid + i * 128;
            int row = id >> 3, c = id & 7;
            unsigned doff = (unsigned)(buf * PSTG_A + row * 64 + (c ^ (row & 7)) * 8) * 2u;
            CP_ASYNC16(sAu + doff, X + (size_t)(m0 + row) * DD_ + kk + c * 8);
        }
#pragma unroll
        for (int i = 0; i < 4; i++) {
            int id = tid + i * 128;
            int row = id >> 3, c = id & 7;
            unsigned doff = (unsigned)(buf * PSTG_B + row * 64 + (c ^ (row & 7)) * 8) * 2u;
            CP_ASYNC16(sBu + doff, W + (size_t)(n0 + row) * DD_ + kk + c * 8);
        }
        CP_COMMIT();
    };

    float acc[4][4][4];
#pragma unroll
    for (int mi = 0; mi < 4; mi++)
#pragma unroll
        for (int ni = 0; ni < 4; ni++)
#pragma unroll
            for (int j = 0; j < 4; j++) acc[mi][ni][j] = 0.f;

    const int arow = wm * 64 + (lane & 15);
    const int ac_hi = (lane >> 4);
    const int brow = wn * 32 + ((lane >> 4) & 1) * 8 + (lane & 7);
    const int bc_hi = (lane >> 3) & 1;

    load_stage(0, 0);
    load_stage(1, 64);

    const int NSTEPS = DD_ / 64;  // 16
    int buf = 0;
    for (int s = 0; s < NSTEPS; s++) {
        if (s + 1 < NSTEPS) {
            CP_WAIT(1);
        } else {
            CP_WAIT(0);
        }
        __syncthreads();   // stage s resident; also proves slot (s-1)%3 drained

        if (s + 2 < NSTEPS) {
            int nb = buf + 2; if (nb >= 3) nb -= 3;
            load_stage(nb, (s + 2) * 64);
        }

#pragma unroll
        for (int k16 = 0; k16 < 4; k16++) {
            unsigned a[4][4], b[4][2];
#pragma unroll
            for (int mi = 0; mi < 4; mi++) {
                int row = arow + mi * 16;
                int c = k16 * 2 + ac_hi;
                unsigned addr = sAu +
                    (unsigned)(buf * PSTG_A + row * 64 + (c ^ (row & 7)) * 8) * 2u;
                ldsm_x4(a[mi][0], a[mi][1], a[mi][2], a[mi][3], addr);
            }
#pragma unroll
            for (int ni2 = 0; ni2 < 2; ni2++) {
                int row = brow + ni2 * 16;
                int c = k16 * 2 + bc_hi;
                unsigned addr = sBu +
                    (unsigned)(buf * PSTG_B + row * 64 + (c ^ (row & 7)) * 8) * 2u;
                ldsm_x4(b[2 * ni2][0], b[2 * ni2][1], b[2 * ni2 + 1][0],
                        b[2 * ni2 + 1][1], addr);
            }
#pragma unroll
            for (int mi = 0; mi < 4; mi++)
#pragma unroll
                for (int ni = 0; ni < 4; ni++) mma16816(acc[mi][ni], a[mi], b[ni]);
        }
        if (++buf >= 3) buf = 0;
    }

    const float sc = (z == 0) ? QSCALE : 1.0f;
#pragma unroll
    for (int mi = 0; mi < 4; mi++) {
        int mrow = m0 + wm * 64 + mi * 16 + g;
        int bidx = mrow >> 11;
        int srow = mrow & (SS_ - 1);
#pragma unroll
        for (int ni = 0; ni < 4; ni++) {
            int ncol = n0 + wn * 32 + ni * 8 + 2 * t;
            float b0 = bias[ncol], b1 = bias[ncol + 1];
            int h = ncol >> 6, d = ncol & 63;
            size_t base = (((size_t)(bidx * HH_ + h) * SS_ + srow) * HDIM + d);
            *(__half2*)(out + base) = __floats2half2_rn(
                (acc[mi][ni][0] + b0) * sc, (acc[mi][ni][1] + b1) * sc);
            *(__half2*)(out + base + 8 * HDIM) = __floats2half2_rn(
                (acc[mi][ni][2] + b0) * sc, (acc[mi][ni][3] + b1) * sc);
        }
    }
}

// ---------------------------------------------------------------------------
// flash attention (unchanged): 128 threads, 4 warps x 16 Q rows, occ 3,
// 128-row stages, f16-acc QK^T, direct exp2 softmax, ones-mma sums.
// ---------------------------------------------------------------------------
#define ASTG_H (128 * 64)

__global__ __launch_bounds__(128, 3) void attn_kernel(float* __restrict__ out) {
    extern __shared__ __half smemA[];
    __half* sK = smemA;
    __half* sV = smemA + 2 * ASTG_H;

    const int tid = threadIdx.x;
    const int warp = tid >> 5, lane = tid & 31;
    const int g = lane >> 2, t = lane & 3;

    const int bh = blockIdx.y;
    const int bidx = bh >> 4, h = bh & 15;
    const int q0 = blockIdx.x * 64;
    const int qr = q0 + warp * 16 + g;

    const __half* Qp = g_Q + ((size_t)bh * SS_ + q0 + warp * 16) * HDIM;
    unsigned qa[4][4];
#pragma unroll
    for (int kt = 0; kt < 4; kt++) {
        const __half* base = Qp + g * HDIM + kt * 16 + 2 * t;
        qa[kt][0] = *(const unsigned*)(base);
        qa[kt][1] = *(const unsigned*)(base + 8 * HDIM);
        qa[kt][2] = *(const unsigned*)(base + 8);
        qa[kt][3] = *(const unsigned*)(base + 8 * HDIM + 8);
    }

    const __half* Kp = g_K + (size_t)bh * SS_ * HDIM;
    const __half* Vp = g_V + (size_t)bh * SS_ * HDIM;
    const unsigned sKu = smem_u32(sK), sVu = smem_u32(sV);

    auto load_stage = [&](int buf, int kv0) {
#pragma unroll
        for (int i = 0; i < 8; i++) {
            int id = tid + i * 128;
            int row = id >> 3, c = id & 7;
            unsigned doff = (unsigned)(buf * ASTG_H + row * 64 + (c ^ (row & 7)) * 8) * 2u;
            CP_ASYNC16(sKu + doff, Kp + (size_t)(kv0 + row) * HDIM + c * 8);
            CP_ASYNC16(sVu + doff, Vp + (size_t)(kv0 + row) * HDIM + c * 8);
        }
        CP_COMMIT();
    };

    const int klo = ((lane >> 4) & 1) * 8 + (lane & 7);
    const int kc_hi = (lane >> 3) & 1;
    const int vrow_l = lane & 15;
    const int vc_hi = (lane >> 4) & 1;

    float o[8][4];
#pragma unroll
    for (int i = 0; i < 8; i++)
#pragma unroll
        for (int j = 0; j < 4; j++) o[i][j] = 0.f;
    float l0 = 0.f, l1 = 0.f;

    const unsigned long long* mb64 = (const unsigned long long*)g_mb;
    const int MROW = SS_ / 64;
    const size_t mbase = ((size_t)bidx * SS_ + qr) * MROW;

    load_stage(0, 0);

    const int NST = SS_ / 128;
    for (int st = 0; st < NST; st++) {
        const int buf = st & 1;
        if (st + 1 < NST) {
            load_stage(buf ^ 1, (st + 1) * 128);
            CP_WAIT(1);
        } else {
            CP_WAIT(0);
        }
        __syncthreads();

#pragma unroll
        for (int sub = 0; sub < 2; sub++) {
            const unsigned sbase = (unsigned)(buf * ASTG_H + sub * (64 * 64));
            const int tile = st * 2 + sub;

            unsigned sc_h[8][2];
#pragma unroll
            for (int i = 0; i < 8; i++) { sc_h[i][0] = 0u; sc_h[i][1] = 0u; }
#pragma unroll
            for (int kt = 0; kt < 4; kt++)
#pragma unroll
                for (int ni2 = 0; ni2 < 4; ni2++) {
                    int row = ni2 * 16 + klo;
                    int c = kt * 2 + kc_hi;
                    unsigned addr = sKu +
                        (sbase + (unsigned)(row * 64 + (c ^ (row & 7)) * 8)) * 2u;
                    unsigned k0, k1, k2, k3;
                    ldsm_x4(k0, k1, k2, k3, addr);
                    { unsigned b2[2] = {k0, k1}; mma16816_h(sc_h[2 * ni2], qa[kt], b2); }
                    { unsigned b2[2] = {k2, k3}; mma16816_h(sc_h[2 * ni2 + 1], qa[kt], b2); }
                }

            unsigned long long mr0 = mb64[mbase + tile];
            unsigned long long mr1 = mb64[mbase + 8 * MROW + tile];
            bool full = __all_sync(0xffffffffu, (mr0 & mr1) == ~0ull);

            unsigned p01[8], p23[8];
            if (full) {
#pragma unroll
                for (int ni = 0; ni < 8; ni++) {
                    p01[ni] = ex2_h2(sc_h[ni][0]);
                    p23[ni] = ex2_h2(sc_h[ni][1]);
                }
            } else {
#pragma unroll
                for (int ni = 0; ni < 8; ni++) {
                    int c0 = ni * 8 + 2 * t, c1 = c0 + 1;
                    unsigned m01 = (((mr0 >> c0) & 1ull) ? 0x0000FFFFu : 0u) |
                                   (((mr0 >> c1) & 1ull) ? 0xFFFF0000u : 0u);
                    unsigned m23 = (((mr1 >> c0) & 1ull) ? 0x0000FFFFu : 0u) |
                                   (((mr1 >> c1) & 1ull) ? 0xFFFF0000u : 0u);
                    p01[ni] = ex2_h2((sc_h[ni][0] & m01) | (NEGH2 & ~m01));
                    p23[ni] = ex2_h2((sc_h[ni][1] & m23) | (NEGH2 & ~m23));
                }
            }

            float lacc[4] = {0.f, 0.f, 0.f, 0.f};
            const unsigned ones[2] = {ONESH2, ONESH2};
#pragma unroll
            for (int kt = 0; kt < 4; kt++) {
                unsigned a[4] = {p01[2 * kt], p23[2 * kt],
                                 p01[2 * kt + 1], p23[2 * kt + 1]};
                mma16816(lacc, a, ones);
            }
            l0 += lacc[0];
            l1 += lacc[2];

#pragma unroll
            for (int kt = 0; kt < 4; kt++) {
                unsigned a[4] = {p01[2 * kt], p23[2 * kt],
                                 p01[2 * kt + 1], p23[2 * kt + 1]};
                int row = kt * 16 + vrow_l;
#pragma unroll
                for (int nd2 = 0; nd2 < 4; nd2++) {
                    int colblk = nd2 * 2 + vc_hi;
                    unsigned addr = sVu +
                        (sbase + (unsigned)(row * 64 + ((colblk ^ (row & 7)) * 8))) * 2u;
                    unsigned v0, v1, v2, v3;
                    ldsm_x4_t(v0, v1, v2, v3, addr);
                    { unsigned b2[2] = {v0, v1}; mma16816(o[2 * nd2], a, b2); }
                    { unsigned b2[2] = {v2, v3}; mma16816(o[2 * nd2 + 1], a, b2); }
                }
            }
        }
        __syncthreads();
    }

    float inv0 = 1.f / l0, inv1 = 1.f / l1;
    float* Op0 = out + ((size_t)bidx * SS_ + qr) * DD_ + h * HDIM;
    float* Op1 = Op0 + 8 * DD_;
#pragma unroll
    for (int nd = 0; nd < 8; nd++) {
        int d = nd * 8 + 2 * t;
        *(float2*)(Op0 + d) = make_float2(o[nd][0] * inv0, o[nd][1] * inv0);
        *(float2*)(Op1 + d) = make_float2(o[nd][2] * inv1, o[nd][3] * inv1);
    }
}

// ---------------------------------------------------------------------------
extern "C" void kernel_launch(void* const* d_in, const int* in_sizes, int n_in,
                              void* d_out, int out_size) {
    (void)in_sizes; (void)n_in; (void)out_size;
    const float* query = (const float*)d_in[0];
    const float* key   = (const float*)d_in[1];
    const float* value = (const float*)d_in[2];
    const int*   mask  = (const int*)d_in[3];
    const float* Wq = (const float*)d_in[4];
    const float* bq = (const float*)d_in[5];
    const float* Wk = (const float*)d_in[6];
    const float* bk = (const float*)d_in[7];
    const float* Wv = (const float*)d_in[8];
    const float* bv = (const float*)d_in[9];

    // One-time side stream + events (created outside capture on first call;
    // no device memory involved). Fork-join via events is capture-legal.
    static cudaStream_t s_side = nullptr;
    static cudaEvent_t ev_fork = nullptr, ev_join = nullptr;
    if (s_side == nullptr) {
        cudaStreamCreateWithFlags(&s_side, cudaStreamNonBlocking);
        cudaEventCreateWithFlags(&ev_fork, cudaEventDisableTiming);
        cudaEventCreateWithFlags(&ev_join, cudaEventDisableTiming);
    }

    // Fork: mask pack runs on the side stream, overlapping conv + proj.
    cudaEventRecord(ev_fork, 0);
    cudaStreamWaitEvent(s_side, ev_fork, 0);
    pack_mask_kernel<<<BB_ * SS_ * SS_ / 8 / 256, 256, 0, s_side>>>(
        (const int4*)mask);
    cudaEventRecord(ev_join, s_side);

    // Main stream: converts -> projections.
    conv_kernel<<<CONV_BLKS, 256>>>((const float4*)query, (const float4*)key,
                                    (const float4*)value,
                                    (const float4*)Wq, (const float4*)Wk,
                                    (const float4*)Wv);

    const int proj_smem = 3 * (PSTG_A + PSTG_B) * (int)sizeof(__half);  // 73728 B
    cudaFuncSetAttribute(proj_kernel, cudaFuncAttributeMaxDynamicSharedMemorySize,
                         proj_smem);
    dim3 gp(DD_ / 64, (BB_ * SS_) / 128, 3);   // (16, 32, 3)
    proj_kernel<<<gp, 128, proj_smem>>>(bq, bk, bv);

    // Join: attn needs the packed mask.
    cudaStreamWaitEvent(0, ev_join, 0);

    const int attn_smem = 4 * ASTG_H * (int)sizeof(__half);  // 65536 B
    cudaFuncSetAttribute(attn_kernel, cudaFuncAttributeMaxDynamicSharedMemorySize,
                         attn_smem);
    dim3 ga(SS_ / 64, BB_ * HH_);    // (32, 32)
    attn_kernel<<<ga, 128, attn_smem>>>((float*)d_out);
}

// round 15
// speedup vs baseline: 1.0429x; 1.0429x over previous
#include <cuda_runtime.h>
#include <cuda_fp16.h>

#define BB_  2
#define SS_  2048
#define DD_  1024
#define HH_  16
#define HDIM 64

// Scratch
__device__ __align__(16) __half g_Q[(size_t)BB_ * HH_ * SS_ * HDIM];
__device__ __align__(16) __half g_K[(size_t)BB_ * HH_ * SS_ * HDIM];
__device__ __align__(16) __half g_V[(size_t)BB_ * HH_ * SS_ * HDIM];
__device__ __align__(16) __half g_Xh[(size_t)3 * BB_ * SS_ * DD_];
__device__ __align__(16) __half g_Wh[(size_t)3 * DD_ * DD_];
__device__ unsigned int g_mb[(size_t)BB_ * SS_ * SS_ / 32];

#define QSCALE 0.1803368801111204f   // 0.125 * log2(e)
#define NEGH2  0xFBFFFBFFu           // half2(-65504, -65504)
#define ONESH2 0x3C003C00u

// ---------------------------------------------------------------------------
__device__ __forceinline__ void mma16816(float (&c)[4], const unsigned (&a)[4],
                                         const unsigned (&b)[2]) {
    asm volatile(
        "mma.sync.aligned.m16n8k16.row.col.f32.f16.f16.f32 "
        "{%0,%1,%2,%3}, {%4,%5,%6,%7}, {%8,%9}, {%0,%1,%2,%3};\n"
        : "+f"(c[0]), "+f"(c[1]), "+f"(c[2]), "+f"(c[3])
        : "r"(a[0]), "r"(a[1]), "r"(a[2]), "r"(a[3]), "r"(b[0]), "r"(b[1]));
}
__device__ __forceinline__ void mma16816_h(unsigned (&c)[2], const unsigned (&a)[4],
                                           const unsigned (&b)[2]) {
    asm volatile(
        "mma.sync.aligned.m16n8k16.row.col.f16.f16.f16.f16 "
        "{%0,%1}, {%2,%3,%4,%5}, {%6,%7}, {%0,%1};\n"
        : "+r"(c[0]), "+r"(c[1])
        : "r"(a[0]), "r"(a[1]), "r"(a[2]), "r"(a[3]), "r"(b[0]), "r"(b[1]));
}

__device__ __forceinline__ unsigned pack_h2(float lo, float hi) {
    __half2 h = __floats2half2_rn(lo, hi);
    return *reinterpret_cast<unsigned*>(&h);
}
__device__ __forceinline__ unsigned ex2_h2(unsigned a) {
    unsigned d;
    asm("ex2.approx.f16x2 %0, %1;" : "=r"(d) : "r"(a));
    return d;
}
__device__ __forceinline__ unsigned smem_u32(const void* p) {
    unsigned r;
    asm("{ .reg .u64 t; cvta.to.shared.u64 t, %1; cvt.u32.u64 %0, t; }"
        : "=r"(r) : "l"(p));
    return r;
}

#define CP_ASYNC16(dst, src) \
    asm volatile("cp.async.cg.shared.global [%0], [%1], 16;\n" ::"r"(dst), "l"(src))
#define CP_COMMIT() asm volatile("cp.async.commit_group;\n")
#define CP_WAIT(n)  asm volatile("cp.async.wait_group %0;\n" ::"n"(n))

__device__ __forceinline__ void ldsm_x4(unsigned& r0, unsigned& r1, unsigned& r2,
                                        unsigned& r3, unsigned addr) {
    asm volatile("ldmatrix.sync.aligned.m8n8.x4.shared.b16 {%0,%1,%2,%3}, [%4];"
                 : "=r"(r0), "=r"(r1), "=r"(r2), "=r"(r3) : "r"(addr));
}
__device__ __forceinline__ void ldsm_x4_t(unsigned& r0, unsigned& r1, unsigned& r2,
                                          unsigned& r3, unsigned addr) {
    asm volatile("ldmatrix.sync.aligned.m8n8.x4.trans.shared.b16 {%0,%1,%2,%3}, [%4];"
                 : "=r"(r0), "=r"(r1), "=r"(r2), "=r"(r3) : "r"(addr));
}

// ---------------------------------------------------------------------------
// fused prep with 2x MLP: mask pack (8 elems/thread) + X/W convert (2x float4).
// blocks: [0,4096) mask; [4096,10240) X; [10240,11776) W.
// ---------------------------------------------------------------------------
#define PREP_MASK_BLKS 4096
#define PREP_X_BLKS    6144
#define PREP_BLKS      11776

__global__ void prep_kernel(const int4* __restrict__ mask,
                            const float4* __restrict__ xq,
                            const float4* __restrict__ xk,
                            const float4* __restrict__ xv,
                            const float4* __restrict__ wq,
                            const float4* __restrict__ wk,
                            const float4* __restrict__ wv) {
    int b = blockIdx.x;
    int tid = threadIdx.x;
    if (b < PREP_MASK_BLKS) {
        int j = b * 256 + tid;
        int4 m0 = mask[2 * j];
        int4 m1 = mask[2 * j + 1];
        unsigned n0 = (unsigned)(m0.x != 0) | ((unsigned)(m0.y != 0) << 1) |
                      ((unsigned)(m0.z != 0) << 2) | ((unsigned)(m0.w != 0) << 3);
        unsigned n1 = (unsigned)(m1.x != 0) | ((unsigned)(m1.y != 0) << 1) |
                      ((unsigned)(m1.z != 0) << 2) | ((unsigned)(m1.w != 0) << 3);
        unsigned byte = n0 | (n1 << 4);
        unsigned v = byte << ((tid & 3) * 8);
        v |= __shfl_xor_sync(0xffffffffu, v, 1);
        v |= __shfl_xor_sync(0xffffffffu, v, 2);
        if ((tid & 3) == 0) g_mb[j >> 2] = v;
    } else if (b < PREP_MASK_BLKS + PREP_X_BLKS) {
        int j = b - PREP_MASK_BLKS;
        int z = j / 2048;
        const float4* src = (z == 0) ? xq : (z == 1) ? xk : xv;
        uint2* dst = (uint2*)g_Xh + (size_t)z * (BB_ * SS_ * DD_ / 4);
        int i = (j - z * 2048) * 512 + tid;
        float4 v0 = src[i];
        float4 v1 = src[i + 256];
        dst[i] = make_uint2(pack_h2(v0.x, v0.y), pack_h2(v0.z, v0.w));
        dst[i + 256] = make_uint2(pack_h2(v1.x, v1.y), pack_h2(v1.z, v1.w));
    } else {
        int j = b - PREP_MASK_BLKS - PREP_X_BLKS;
        int z = j >> 9;
        const float4* src = (z == 0) ? wq : (z == 1) ? wk : wv;
        uint2* dst = (uint2*)g_Wh + (size_t)z * (DD_ * DD_ / 4);
        int i = (j & 511) * 512 + tid;
        float4 v0 = src[i];
        float4 v1 = src[i + 256];
        dst[i] = make_uint2(pack_h2(v0.x, v0.y), pack_h2(v0.z, v0.w));
        dst[i + 256] = make_uint2(pack_h2(v1.x, v1.y), pack_h2(v1.z, v1.w));
    }
}

// ---------------------------------------------------------------------------
// fused projection GEMMs (z=0/1/2 -> Q/K/V), fp16 datapath.
// 128x64 tiles, 128 threads (4 warps, 64x32 each), 3-stage cp.async,
// one barrier per k-step, occupancy 3.
// ---------------------------------------------------------------------------
#define PSTG_A 8192          // halfs per A stage (128 x 64)
#define PSTG_B 4096          // halfs per B stage (64 x 64)

__global__ __launch_bounds__(128, 3) void proj_kernel(const float* __restrict__ bqp,
                                                      const float* __restrict__ bkp,
                                                      const float* __restrict__ bvp) {
    extern __shared__ __half smemh[];
    __half* sA = smemh;                 // [3][8192]
    __half* sB = smemh + 3 * PSTG_A;    // [3][4096]

    const int z = blockIdx.z;
    const __half* X = g_Xh + (size_t)z * BB_ * SS_ * DD_;
    const __half* W = g_Wh + (size_t)z * DD_ * DD_;
    __half* out = (z == 0) ? g_Q : (z == 1) ? g_K : g_V;
    const float* bias = (z == 0) ? bqp : (z == 1) ? bkp : bvp;

    const int tid = threadIdx.x;
    const int warp = tid >> 5, lane = tid & 31;
    const int g = lane >> 2, t = lane & 3;
    const int wm = warp & 1, wn = warp >> 1;
    const int m0 = blockIdx.y * 128, n0 = blockIdx.x * 64;

    const unsigned sAu = smem_u32(sA), sBu = smem_u32(sB);

    auto load_stage = [&](int buf, int kk) {
#pragma unroll
        for (int i = 0; i < 8; i++) {
            int id = tid + i * 128;
            int row = id >> 3, c = id & 7;
            unsigned doff = (unsigned)(buf * PSTG_A + row * 64 + (c ^ (row & 7)) * 8) * 2u;
            CP_ASYNC16(sAu + doff, X + (size_t)(m0 + row) * DD_ + kk + c * 8);
        }
#pragma unroll
        for (int i = 0; i < 4; i++) {
            int id = tid + i * 128;
            int row = id >> 3, c = id & 7;
            unsigned doff = (unsigned)(buf * PSTG_B + row * 64 + (c ^ (row & 7)) * 8) * 2u;
            CP_ASYNC16(sBu + doff, W + (size_t)(n0 + row) * DD_ + kk + c * 8);
        }
        CP_COMMIT();
    };

    float acc[4][4][4];
#pragma unroll
    for (int mi = 0; mi < 4; mi++)
#pragma unroll
        for (int ni = 0; ni < 4; ni++)
#pragma unroll
            for (int j = 0; j < 4; j++) acc[mi][ni][j] = 0.f;

    const int arow = wm * 64 + (lane & 15);
    const int ac_hi = (lane >> 4);
    const int brow = wn * 32 + ((lane >> 4) & 1) * 8 + (lane & 7);
    const int bc_hi = (lane >> 3) & 1;

    load_stage(0, 0);
    load_stage(1, 64);

    const int NSTEPS = DD_ / 64;  // 16
    int buf = 0;
    for (int s = 0; s < NSTEPS; s++) {
        if (s + 1 < NSTEPS) {
            CP_WAIT(1);
        } else {
            CP_WAIT(0);
        }
        __syncthreads();   // stage s resident; also proves slot (s-1)%3 drained

        if (s + 2 < NSTEPS) {
            int nb = buf + 2; if (nb >= 3) nb -= 3;
            load_stage(nb, (s + 2) * 64);
        }

#pragma unroll
        for (int k16 = 0; k16 < 4; k16++) {
            unsigned a[4][4], b[4][2];
#pragma unroll
            for (int mi = 0; mi < 4; mi++) {
                int row = arow + mi * 16;
                int c = k16 * 2 + ac_hi;
                unsigned addr = sAu +
                    (unsigned)(buf * PSTG_A + row * 64 + (c ^ (row & 7)) * 8) * 2u;
                ldsm_x4(a[mi][0], a[mi][1], a[mi][2], a[mi][3], addr);
            }
#pragma unroll
            for (int ni2 = 0; ni2 < 2; ni2++) {
                int row = brow + ni2 * 16;
                int c = k16 * 2 + bc_hi;
                unsigned addr = sBu +
                    (unsigned)(buf * PSTG_B + row * 64 + (c ^ (row & 7)) * 8) * 2u;
                ldsm_x4(b[2 * ni2][0], b[2 * ni2][1], b[2 * ni2 + 1][0],
                        b[2 * ni2 + 1][1], addr);
            }
#pragma unroll
            for (int mi = 0; mi < 4; mi++)
#pragma unroll
                for (int ni = 0; ni < 4; ni++) mma16816(acc[mi][ni], a[mi], b[ni]);
        }
        if (++buf >= 3) buf = 0;
    }

    const float sc = (z == 0) ? QSCALE : 1.0f;
#pragma unroll
    for (int mi = 0; mi < 4; mi++) {
        int mrow = m0 + wm * 64 + mi * 16 + g;
        int bidx = mrow >> 11;
        int srow = mrow & (SS_ - 1);
#pragma unroll
        for (int ni = 0; ni < 4; ni++) {
            int ncol = n0 + wn * 32 + ni * 8 + 2 * t;
            float b0 = bias[ncol], b1 = bias[ncol + 1];
            int h = ncol >> 6, d = ncol & 63;
            size_t base = (((size_t)(bidx * HH_ + h) * SS_ + srow) * HDIM + d);
            *(__half2*)(out + base) = __floats2half2_rn(
                (acc[mi][ni][0] + b0) * sc, (acc[mi][ni][1] + b1) * sc);
            *(__half2*)(out + base + 8 * HDIM) = __floats2half2_rn(
                (acc[mi][ni][2] + b0) * sc, (acc[mi][ni][3] + b1) * sc);
        }
    }
}

// ---------------------------------------------------------------------------
// flash attention: 128 threads, 4 warps x 16 Q rows (Q block 64), OCC 4
// (register-capped at 128, 32 KB smem: 64-row double-buffered KV stages).
// f16-acc QK^T, direct exp2 softmax, ones-mma row sums.
// ---------------------------------------------------------------------------
#define ASTG_H (64 * 64)   // halfs per tensor per stage

__global__ __launch_bounds__(128, 4) void attn_kernel(float* __restrict__ out) {
    extern __shared__ __half smemA[];
    __half* sK = smemA;                 // [2][4096]
    __half* sV = smemA + 2 * ASTG_H;    // [2][4096]

    const int tid = threadIdx.x;
    const int warp = tid >> 5, lane = tid & 31;
    const int g = lane >> 2, t = lane & 3;

    const int bh = blockIdx.y;
    const int bidx = bh >> 4, h = bh & 15;
    const int q0 = blockIdx.x * 64;
    const int qr = q0 + warp * 16 + g;

    const __half* Qp = g_Q + ((size_t)bh * SS_ + q0 + warp * 16) * HDIM;
    unsigned qa[4][4];
#pragma unroll
    for (int kt = 0; kt < 4; kt++) {
        const __half* base = Qp + g * HDIM + kt * 16 + 2 * t;
        qa[kt][0] = *(const unsigned*)(base);
        qa[kt][1] = *(const unsigned*)(base + 8 * HDIM);
        qa[kt][2] = *(const unsigned*)(base + 8);
        qa[kt][3] = *(const unsigned*)(base + 8 * HDIM + 8);
    }

    const __half* Kp = g_K + (size_t)bh * SS_ * HDIM;
    const __half* Vp = g_V + (size_t)bh * SS_ * HDIM;
    const unsigned sKu = smem_u32(sK), sVu = smem_u32(sV);

    auto load_tile = [&](int buf, int kv0) {
#pragma unroll
        for (int i = 0; i < 4; i++) {
            int id = tid + i * 128;
            int row = id >> 3, c = id & 7;
            unsigned doff = (unsigned)(buf * ASTG_H + row * 64 + (c ^ (row & 7)) * 8) * 2u;
            CP_ASYNC16(sKu + doff, Kp + (size_t)(kv0 + row) * HDIM + c * 8);
            CP_ASYNC16(sVu + doff, Vp + (size_t)(kv0 + row) * HDIM + c * 8);
        }
        CP_COMMIT();
    };

    const int klo = ((lane >> 4) & 1) * 8 + (lane & 7);
    const int kc_hi = (lane >> 3) & 1;
    const int vrow_l = lane & 15;
    const int vc_hi = (lane >> 4) & 1;

    float o[8][4];
#pragma unroll
    for (int i = 0; i < 8; i++)
#pragma unroll
        for (int j = 0; j < 4; j++) o[i][j] = 0.f;
    float l0 = 0.f, l1 = 0.f;

    const unsigned long long* mb64 = (const unsigned long long*)g_mb;
    const int MROW = SS_ / 64;
    const size_t mbase = ((size_t)bidx * SS_ + qr) * MROW;

    load_tile(0, 0);

    const int NT = SS_ / 64;   // 32 tiles
    for (int tile = 0; tile < NT; tile++) {
        const int buf = tile & 1;
        if (tile + 1 < NT) {
            load_tile(buf ^ 1, (tile + 1) * 64);
            CP_WAIT(1);
        } else {
            CP_WAIT(0);
        }
        __syncthreads();

        const unsigned sbase = (unsigned)(buf * ASTG_H);

        // S = Q K^T (f16 accumulators, exp2 domain)
        unsigned sc_h[8][2];
#pragma unroll
        for (int i = 0; i < 8; i++) { sc_h[i][0] = 0u; sc_h[i][1] = 0u; }
#pragma unroll
        for (int kt = 0; kt < 4; kt++)
#pragma unroll
            for (int ni2 = 0; ni2 < 4; ni2++) {
                int row = ni2 * 16 + klo;
                int c = kt * 2 + kc_hi;
                unsigned addr = sKu +
                    (sbase + (unsigned)(row * 64 + (c ^ (row & 7)) * 8)) * 2u;
                unsigned k0, k1, k2, k3;
                ldsm_x4(k0, k1, k2, k3, addr);
                { unsigned b2[2] = {k0, k1}; mma16816_h(sc_h[2 * ni2], qa[kt], b2); }
                { unsigned b2[2] = {k2, k3}; mma16816_h(sc_h[2 * ni2 + 1], qa[kt], b2); }
            }

        // mask, then P = exp2(S) directly
        unsigned long long mr0 = mb64[mbase + tile];
        unsigned long long mr1 = mb64[mbase + 8 * MROW + tile];
        bool full = __all_sync(0xffffffffu, (mr0 & mr1) == ~0ull);

        unsigned p01[8], p23[8];
        if (full) {
#pragma unroll
            for (int ni = 0; ni < 8; ni++) {
                p01[ni] = ex2_h2(sc_h[ni][0]);
                p23[ni] = ex2_h2(sc_h[ni][1]);
            }
        } else {
#pragma unroll
            for (int ni = 0; ni < 8; ni++) {
                int c0 = ni * 8 + 2 * t, c1 = c0 + 1;
                unsigned m01 = (((mr0 >> c0) & 1ull) ? 0x0000FFFFu : 0u) |
                               (((mr0 >> c1) & 1ull) ? 0xFFFF0000u : 0u);
                unsigned m23 = (((mr1 >> c0) & 1ull) ? 0x0000FFFFu : 0u) |
                               (((mr1 >> c1) & 1ull) ? 0xFFFF0000u : 0u);
                p01[ni] = ex2_h2((sc_h[ni][0] & m01) | (NEGH2 & ~m01));
                p23[ni] = ex2_h2((sc_h[ni][1] & m23) | (NEGH2 & ~m23));
            }
        }

        // row sums via ones-mma (f32, exact)
        float lacc[4] = {0.f, 0.f, 0.f, 0.f};
        const unsigned ones[2] = {ONESH2, ONESH2};
#pragma unroll
        for (int kt = 0; kt < 4; kt++) {
            unsigned a[4] = {p01[2 * kt], p23[2 * kt],
                             p01[2 * kt + 1], p23[2 * kt + 1]};
            mma16816(lacc, a, ones);
        }
        l0 += lacc[0];
        l1 += lacc[2];

        // O += P V
#pragma unroll
        for (int kt = 0; kt < 4; kt++) {
            unsigned a[4] = {p01[2 * kt], p23[2 * kt],
                             p01[2 * kt + 1], p23[2 * kt + 1]};
            int row = kt * 16 + vrow_l;
#pragma unroll
            for (int nd2 = 0; nd2 < 4; nd2++) {
                int colblk = nd2 * 2 + vc_hi;
                unsigned addr = sVu +
                    (sbase + (unsigned)(row * 64 + ((colblk ^ (row & 7)) * 8))) * 2u;
                unsigned v0, v1, v2, v3;
                ldsm_x4_t(v0, v1, v2, v3, addr);
                { unsigned b2[2] = {v0, v1}; mma16816(o[2 * nd2], a, b2); }
                { unsigned b2[2] = {v2, v3}; mma16816(o[2 * nd2 + 1], a, b2); }
            }
        }
        __syncthreads();
    }

    float inv0 = 1.f / l0, inv1 = 1.f / l1;
    float* Op0 = out + ((size_t)bidx * SS_ + qr) * DD_ + h * HDIM;
    float* Op1 = Op0 + 8 * DD_;
#pragma unroll
    for (int nd = 0; nd < 8; nd++) {
        int d = nd * 8 + 2 * t;
        *(float2*)(Op0 + d) = make_float2(o[nd][0] * inv0, o[nd][1] * inv0);
        *(float2*)(Op1 + d) = make_float2(o[nd][2] * inv1, o[nd][3] * inv1);
    }
}

// ---------------------------------------------------------------------------
extern "C" void kernel_launch(void* const* d_in, const int* in_sizes, int n_in,
                              void* d_out, int out_size) {
    (void)in_sizes; (void)n_in; (void)out_size;
    const float* query = (const float*)d_in[0];
    const float* key   = (const float*)d_in[1];
    const float* value = (const float*)d_in[2];
    const int*   mask  = (const int*)d_in[3];
    const float* Wq = (const float*)d_in[4];
    const float* bq = (const float*)d_in[5];
    const float* Wk = (const float*)d_in[6];
    const float* bk = (const float*)d_in[7];
    const float* Wv = (const float*)d_in[8];
    const float* bv = (const float*)d_in[9];

    prep_kernel<<<PREP_BLKS, 256>>>((const int4*)mask,
                                    (const float4*)query, (const float4*)key,
                                    (const float4*)value,
                                    (const float4*)Wq, (const float4*)Wk,
                                    (const float4*)Wv);

    const int proj_smem = 3 * (PSTG_A + PSTG_B) * (int)sizeof(__half);  // 73728 B
    cudaFuncSetAttribute(proj_kernel, cudaFuncAttributeMaxDynamicSharedMemorySize,
                         proj_smem);
    dim3 gp(DD_ / 64, (BB_ * SS_) / 128, 3);   // (16, 32, 3)
    proj_kernel<<<gp, 128, proj_smem>>>(bq, bk, bv);

    const int attn_smem = 4 * ASTG_H * (int)sizeof(__half);  // 32768 B
    cudaFuncSetAttribute(attn_kernel, cudaFuncAttributeMaxDynamicSharedMemorySize,
                         attn_smem);
    dim3 ga(SS_ / 64, BB_ * HH_);    // (32, 32)
    attn_kernel<<<ga, 128, attn_smem>>>((float*)d_out);
}

// round 16
// speedup vs baseline: 1.0575x; 1.0140x over previous
#include <cuda_runtime.h>
#include <cuda_fp16.h>

#define BB_  2
#define SS_  2048
#define DD_  1024
#define HH_  16
#define HDIM 64

// Scratch
__device__ __align__(16) __half g_Q[(size_t)BB_ * HH_ * SS_ * HDIM];
__device__ __align__(16) __half g_K[(size_t)BB_ * HH_ * SS_ * HDIM];
__device__ __align__(16) __half g_V[(size_t)BB_ * HH_ * SS_ * HDIM];
__device__ __align__(16) __half g_Xh[(size_t)3 * BB_ * SS_ * DD_];
__device__ __align__(16) __half g_Wh[(size_t)3 * DD_ * DD_];
__device__ unsigned int g_mb[(size_t)BB_ * SS_ * SS_ / 32];

#define QSCALE 0.1803368801111204f   // 0.125 * log2(e)
#define NEGH2  0xFBFFFBFFu           // half2(-65504, -65504)
#define ONESH2 0x3C003C00u

// ---------------------------------------------------------------------------
__device__ __forceinline__ void mma16816(float (&c)[4], const unsigned (&a)[4],
                                         const unsigned (&b)[2]) {
    asm volatile(
        "mma.sync.aligned.m16n8k16.row.col.f32.f16.f16.f32 "
        "{%0,%1,%2,%3}, {%4,%5,%6,%7}, {%8,%9}, {%0,%1,%2,%3};\n"
        : "+f"(c[0]), "+f"(c[1]), "+f"(c[2]), "+f"(c[3])
        : "r"(a[0]), "r"(a[1]), "r"(a[2]), "r"(a[3]), "r"(b[0]), "r"(b[1]));
}
__device__ __forceinline__ void mma16816_h(unsigned (&c)[2], const unsigned (&a)[4],
                                           const unsigned (&b)[2]) {
    asm volatile(
        "mma.sync.aligned.m16n8k16.row.col.f16.f16.f16.f16 "
        "{%0,%1}, {%2,%3,%4,%5}, {%6,%7}, {%0,%1};\n"
        : "+r"(c[0]), "+r"(c[1])
        : "r"(a[0]), "r"(a[1]), "r"(a[2]), "r"(a[3]), "r"(b[0]), "r"(b[1]));
}

__device__ __forceinline__ unsigned pack_h2(float lo, float hi) {
    __half2 h = __floats2half2_rn(lo, hi);
    return *reinterpret_cast<unsigned*>(&h);
}
__device__ __forceinline__ unsigned ex2_h2(unsigned a) {
    unsigned d;
    asm("ex2.approx.f16x2 %0, %1;" : "=r"(d) : "r"(a));
    return d;
}
__device__ __forceinline__ unsigned smem_u32(const void* p) {
    unsigned r;
    asm("{ .reg .u64 t; cvta.to.shared.u64 t, %1; cvt.u32.u64 %0, t; }"
        : "=r"(r) : "l"(p));
    return r;
}

#define CP_ASYNC16(dst, src) \
    asm volatile("cp.async.cg.shared.global [%0], [%1], 16;\n" ::"r"(dst), "l"(src))
#define CP_COMMIT() asm volatile("cp.async.commit_group;\n")
#define CP_WAIT(n)  asm volatile("cp.async.wait_group %0;\n" ::"n"(n))

__device__ __forceinline__ void ldsm_x4(unsigned& r0, unsigned& r1, unsigned& r2,
                                        unsigned& r3, unsigned addr) {
    asm volatile("ldmatrix.sync.aligned.m8n8.x4.shared.b16 {%0,%1,%2,%3}, [%4];"
                 : "=r"(r0), "=r"(r1), "=r"(r2), "=r"(r3) : "r"(addr));
}
__device__ __forceinline__ void ldsm_x4_t(unsigned& r0, unsigned& r1, unsigned& r2,
                                          unsigned& r3, unsigned addr) {
    asm volatile("ldmatrix.sync.aligned.m8n8.x4.trans.shared.b16 {%0,%1,%2,%3}, [%4];"
                 : "=r"(r0), "=r"(r1), "=r"(r2), "=r"(r3) : "r"(addr));
}

// ---------------------------------------------------------------------------
// fused prep with 2x MLP: mask pack (8 elems/thread) + X/W convert (2x float4).
// ---------------------------------------------------------------------------
#define PREP_MASK_BLKS 4096
#define PREP_X_BLKS    6144
#define PREP_BLKS      11776

__global__ void prep_kernel(const int4* __restrict__ mask,
                            const float4* __restrict__ xq,
                            const float4* __restrict__ xk,
                            const float4* __restrict__ xv,
                            const float4* __restrict__ wq,
                            const float4* __restrict__ wk,
                            const float4* __restrict__ wv) {
    int b = blockIdx.x;
    int tid = threadIdx.x;
    if (b < PREP_MASK_BLKS) {
        int j = b * 256 + tid;
        int4 m0 = mask[2 * j];
        int4 m1 = mask[2 * j + 1];
        unsigned n0 = (unsigned)(m0.x != 0) | ((unsigned)(m0.y != 0) << 1) |
                      ((unsigned)(m0.z != 0) << 2) | ((unsigned)(m0.w != 0) << 3);
        unsigned n1 = (unsigned)(m1.x != 0) | ((unsigned)(m1.y != 0) << 1) |
                      ((unsigned)(m1.z != 0) << 2) | ((unsigned)(m1.w != 0) << 3);
        unsigned byte = n0 | (n1 << 4);
        unsigned v = byte << ((tid & 3) * 8);
        v |= __shfl_xor_sync(0xffffffffu, v, 1);
        v |= __shfl_xor_sync(0xffffffffu, v, 2);
        if ((tid & 3) == 0) g_mb[j >> 2] = v;
    } else if (b < PREP_MASK_BLKS + PREP_X_BLKS) {
        int j = b - PREP_MASK_BLKS;
        int z = j / 2048;
        const float4* src = (z == 0) ? xq : (z == 1) ? xk : xv;
        uint2* dst = (uint2*)g_Xh + (size_t)z * (BB_ * SS_ * DD_ / 4);
        int i = (j - z * 2048) * 512 + tid;
        float4 v0 = src[i];
        float4 v1 = src[i + 256];
        dst[i] = make_uint2(pack_h2(v0.x, v0.y), pack_h2(v0.z, v0.w));
        dst[i + 256] = make_uint2(pack_h2(v1.x, v1.y), pack_h2(v1.z, v1.w));
    } else {
        int j = b - PREP_MASK_BLKS - PREP_X_BLKS;
        int z = j >> 9;
        const float4* src = (z == 0) ? wq : (z == 1) ? wk : wv;
        uint2* dst = (uint2*)g_Wh + (size_t)z * (DD_ * DD_ / 4);
        int i = (j & 511) * 512 + tid;
        float4 v0 = src[i];
        float4 v1 = src[i + 256];
        dst[i] = make_uint2(pack_h2(v0.x, v0.y), pack_h2(v0.z, v0.w));
        dst[i + 256] = make_uint2(pack_h2(v1.x, v1.y), pack_h2(v1.z, v1.w));
    }
}

// ---------------------------------------------------------------------------
// fused projection GEMMs (z=0/1/2 -> Q/K/V), fp16 datapath.
// 128x64 tiles, 128 threads, 3-stage cp.async, one barrier per k-step, occ 3.
// Epilogue staged through smem for fully coalesced 16B stores.
// ---------------------------------------------------------------------------
#define PSTG_A 8192          // halfs per A stage (128 x 64)
#define PSTG_B 4096          // halfs per B stage (64 x 64)
#define EPI_STRIDE 72        // padded halfs per staged output row

__global__ __launch_bounds__(128, 3) void proj_kernel(const float* __restrict__ bqp,
                                                      const float* __restrict__ bkp,
                                                      const float* __restrict__ bvp) {
    extern __shared__ __half smemh[];
    __half* sA = smemh;                 // [3][8192]
    __half* sB = smemh + 3 * PSTG_A;    // [3][4096]
    __half* sO = smemh;                 // epilogue staging (reuses sA region)

    const int z = blockIdx.z;
    const __half* X = g_Xh + (size_t)z * BB_ * SS_ * DD_;
    const __half* W = g_Wh + (size_t)z * DD_ * DD_;
    __half* out = (z == 0) ? g_Q : (z == 1) ? g_K : g_V;
    const float* bias = (z == 0) ? bqp : (z == 1) ? bkp : bvp;

    const int tid = threadIdx.x;
    const int warp = tid >> 5, lane = tid & 31;
    const int g = lane >> 2, t = lane & 3;
    const int wm = warp & 1, wn = warp >> 1;
    const int m0 = blockIdx.y * 128, n0 = blockIdx.x * 64;

    const unsigned sAu = smem_u32(sA), sBu = smem_u32(sB);

    auto load_stage = [&](int buf, int kk) {
#pragma unroll
        for (int i = 0; i < 8; i++) {
            int id = tid + i * 128;
            int row = id >> 3, c = id & 7;
            unsigned doff = (unsigned)(buf * PSTG_A + row * 64 + (c ^ (row & 7)) * 8) * 2u;
            CP_ASYNC16(sAu + doff, X + (size_t)(m0 + row) * DD_ + kk + c * 8);
        }
#pragma unroll
        for (int i = 0; i < 4; i++) {
            int id = tid + i * 128;
            int row = id >> 3, c = id & 7;
            unsigned doff = (unsigned)(buf * PSTG_B + row * 64 + (c ^ (row & 7)) * 8) * 2u;
            CP_ASYNC16(sBu + doff, W + (size_t)(n0 + row) * DD_ + kk + c * 8);
        }
        CP_COMMIT();
    };

    float acc[4][4][4];
#pragma unroll
    for (int mi = 0; mi < 4; mi++)
#pragma unroll
        for (int ni = 0; ni < 4; ni++)
#pragma unroll
            for (int j = 0; j < 4; j++) acc[mi][ni][j] = 0.f;

    const int arow = wm * 64 + (lane & 15);
    const int ac_hi = (lane >> 4);
    const int brow = wn * 32 + ((lane >> 4) & 1) * 8 + (lane & 7);
    const int bc_hi = (lane >> 3) & 1;

    load_stage(0, 0);
    load_stage(1, 64);

    const int NSTEPS = DD_ / 64;  // 16
    int buf = 0;
    for (int s = 0; s < NSTEPS; s++) {
        if (s + 1 < NSTEPS) {
            CP_WAIT(1);
        } else {
            CP_WAIT(0);
        }
        __syncthreads();

        if (s + 2 < NSTEPS) {
            int nb = buf + 2; if (nb >= 3) nb -= 3;
            load_stage(nb, (s + 2) * 64);
        }

#pragma unroll
        for (int k16 = 0; k16 < 4; k16++) {
            unsigned a[4][4], b[4][2];
#pragma unroll
            for (int mi = 0; mi < 4; mi++) {
                int row = arow + mi * 16;
                int c = k16 * 2 + ac_hi;
                unsigned addr = sAu +
                    (unsigned)(buf * PSTG_A + row * 64 + (c ^ (row & 7)) * 8) * 2u;
                ldsm_x4(a[mi][0], a[mi][1], a[mi][2], a[mi][3], addr);
            }
#pragma unroll
            for (int ni2 = 0; ni2 < 2; ni2++) {
                int row = brow + ni2 * 16;
                int c = k16 * 2 + bc_hi;
                unsigned addr = sBu +
                    (unsigned)(buf * PSTG_B + row * 64 + (c ^ (row & 7)) * 8) * 2u;
                ldsm_x4(b[2 * ni2][0], b[2 * ni2][1], b[2 * ni2 + 1][0],
                        b[2 * ni2 + 1][1], addr);
            }
#pragma unroll
            for (int mi = 0; mi < 4; mi++)
#pragma unroll
                for (int ni = 0; ni < 4; ni++) mma16816(acc[mi][ni], a[mi], b[ni]);
        }
        if (++buf >= 3) buf = 0;
    }

    // Epilogue: bias + scale in registers, stage to smem (padded rows),
    // then one contiguous 16 KB streaming store.
    const float sc = (z == 0) ? QSCALE : 1.0f;
    __syncthreads();   // all k-loop smem reads done before overwrite
#pragma unroll
    for (int mi = 0; mi < 4; mi++) {
        int r = wm * 64 + mi * 16 + g;         // local row (+8 for hi pair)
#pragma unroll
        for (int ni = 0; ni < 4; ni++) {
            int col = wn * 32 + ni * 8 + 2 * t;  // local col
            float b0 = bias[n0 + col], b1 = bias[n0 + col + 1];
            *(__half2*)(sO + r * EPI_STRIDE + col) = __floats2half2_rn(
                (acc[mi][ni][0] + b0) * sc, (acc[mi][ni][1] + b1) * sc);
            *(__half2*)(sO + (r + 8) * EPI_STRIDE + col) = __floats2half2_rn(
                (acc[mi][ni][2] + b0) * sc, (acc[mi][ni][3] + b1) * sc);
        }
    }
    __syncthreads();

    // Whole tile is contiguous in output: (bidx, h) constant, srow consecutive.
    {
        const int bidx = m0 >> 11;
        const int srow0 = m0 & (SS_ - 1);
        const int h = n0 >> 6;
        __half* op = out + (((size_t)(bidx * HH_ + h) * SS_ + srow0) * HDIM);
#pragma unroll
        for (int i = 0; i < 8; i++) {
            int id = tid + i * 128;           // 0..1023 -> row*8 + chunk
            int row = id >> 3, ch = id & 7;
            uint4 v = *(const uint4*)(sO + row * EPI_STRIDE + ch * 8);
            *(uint4*)(op + row * HDIM + ch * 8) = v;
        }
    }
}

// ---------------------------------------------------------------------------
// flash attention: 128 threads, 4 warps x 16 Q rows (Q block 64), occ 4.
// 3-stage 64-row cp.async ring, ONE barrier per tile (48 KB smem).
// f16-acc QK^T, direct exp2 softmax, ones-mma row sums.
// ---------------------------------------------------------------------------
#define ASTG_H (64 * 64)   // halfs per tensor per stage

__global__ __launch_bounds__(128, 4) void attn_kernel(float* __restrict__ out) {
    extern __shared__ __half smemA[];
    __half* sK = smemA;                 // [3][4096]
    __half* sV = smemA + 3 * ASTG_H;    // [3][4096]

    const int tid = threadIdx.x;
    const int warp = tid >> 5, lane = tid & 31;
    const int g = lane >> 2, t = lane & 3;

    const int bh = blockIdx.y;
    const int bidx = bh >> 4, h = bh & 15;
    const int q0 = blockIdx.x * 64;
    const int qr = q0 + warp * 16 + g;

    const __half* Qp = g_Q + ((size_t)bh * SS_ + q0 + warp * 16) * HDIM;
    unsigned qa[4][4];
#pragma unroll
    for (int kt = 0; kt < 4; kt++) {
        const __half* base = Qp + g * HDIM + kt * 16 + 2 * t;
        qa[kt][0] = *(const unsigned*)(base);
        qa[kt][1] = *(const unsigned*)(base + 8 * HDIM);
        qa[kt][2] = *(const unsigned*)(base + 8);
        qa[kt][3] = *(const unsigned*)(base + 8 * HDIM + 8);
    }

    const __half* Kp = g_K + (size_t)bh * SS_ * HDIM;
    const __half* Vp = g_V + (size_t)bh * SS_ * HDIM;
    const unsigned sKu = smem_u32(sK), sVu = smem_u32(sV);

    auto load_tile = [&](int buf, int kv0) {
#pragma unroll
        for (int i = 0; i < 4; i++) {
            int id = tid + i * 128;
            int row = id >> 3, c = id & 7;
            unsigned doff = (unsigned)(buf * ASTG_H + row * 64 + (c ^ (row & 7)) * 8) * 2u;
            CP_ASYNC16(sKu + doff, Kp + (size_t)(kv0 + row) * HDIM + c * 8);
            CP_ASYNC16(sVu + doff, Vp + (size_t)(kv0 + row) * HDIM + c * 8);
        }
        CP_COMMIT();
    };

    const int klo = ((lane >> 4) & 1) * 8 + (lane & 7);
    const int kc_hi = (lane >> 3) & 1;
    const int vrow_l = lane & 15;
    const int vc_hi = (lane >> 4) & 1;

    float o[8][4];
#pragma unroll
    for (int i = 0; i < 8; i++)
#pragma unroll
        for (int j = 0; j < 4; j++) o[i][j] = 0.f;
    float l0 = 0.f, l1 = 0.f;

    const unsigned long long* mb64 = (const unsigned long long*)g_mb;
    const int MROW = SS_ / 64;
    const size_t mbase = ((size_t)bidx * SS_ + qr) * MROW;

    load_tile(0, 0);
    load_tile(1, 64);

    const int NT = SS_ / 64;   // 32 tiles
    int buf = 0;
    for (int tile = 0; tile < NT; tile++) {
        if (tile + 1 < NT) {
            CP_WAIT(1);
        } else {
            CP_WAIT(0);
        }
        __syncthreads();   // tile resident; also proves slot (tile-1)%3 drained

        if (tile + 2 < NT) {
            int nb = buf + 2; if (nb >= 3) nb -= 3;
            load_tile(nb, (tile + 2) * 64);
        }

        const unsigned sbase = (unsigned)(buf * ASTG_H);

        // S = Q K^T (f16 accumulators, exp2 domain)
        unsigned sc_h[8][2];
#pragma unroll
        for (int i = 0; i < 8; i++) { sc_h[i][0] = 0u; sc_h[i][1] = 0u; }
#pragma unroll
        for (int kt = 0; kt < 4; kt++)
#pragma unroll
            for (int ni2 = 0; ni2 < 4; ni2++) {
                int row = ni2 * 16 + klo;
                int c = kt * 2 + kc_hi;
                unsigned addr = sKu +
                    (sbase + (unsigned)(row * 64 + (c ^ (row & 7)) * 8)) * 2u;
                unsigned k0, k1, k2, k3;
                ldsm_x4(k0, k1, k2, k3, addr);
                { unsigned b2[2] = {k0, k1}; mma16816_h(sc_h[2 * ni2], qa[kt], b2); }
                { unsigned b2[2] = {k2, k3}; mma16816_h(sc_h[2 * ni2 + 1], qa[kt], b2); }
            }

        // mask, then P = exp2(S) directly
        unsigned long long mr0 = mb64[mbase + tile];
        unsigned long long mr1 = mb64[mbase + 8 * MROW + tile];
        bool full = __all_sync(0xffffffffu, (mr0 & mr1) == ~0ull);

        unsigned p01[8], p23[8];
        if (full) {
#pragma unroll
            for (int ni = 0; ni < 8; ni++) {
                p01[ni] = ex2_h2(sc_h[ni][0]);
                p23[ni] = ex2_h2(sc_h[ni][1]);
            }
        } else {
#pragma unroll
            for (int ni = 0; ni < 8; ni++) {
                int c0 = ni * 8 + 2 * t, c1 = c0 + 1;
                unsigned m01 = (((mr0 >> c0) & 1ull) ? 0x0000FFFFu : 0u) |
                               (((mr0 >> c1) & 1ull) ? 0xFFFF0000u : 0u);
                unsigned m23 = (((mr1 >> c0) & 1ull) ? 0x0000FFFFu : 0u) |
                               (((mr1 >> c1) & 1ull) ? 0xFFFF0000u : 0u);
                p01[ni] = ex2_h2((sc_h[ni][0] & m01) | (NEGH2 & ~m01));
                p23[ni] = ex2_h2((sc_h[ni][1] & m23) | (NEGH2 & ~m23));
            }
        }

        // row sums via ones-mma (f32, exact)
        float lacc[4] = {0.f, 0.f, 0.f, 0.f};
        const unsigned ones[2] = {ONESH2, ONESH2};
#pragma unroll
        for (int kt = 0; kt < 4; kt++) {
            unsigned a[4] = {p01[2 * kt], p23[2 * kt],
                             p01[2 * kt + 1], p23[2 * kt + 1]};
            mma16816(lacc, a, ones);
        }
        l0 += lacc[0];
        l1 += lacc[2];

        // O += P V
#pragma unroll
        for (int kt = 0; kt < 4; kt++) {
            unsigned a[4] = {p01[2 * kt], p23[2 * kt],
                             p01[2 * kt + 1], p23[2 * kt + 1]};
            int row = kt * 16 + vrow_l;
#pragma unroll
            for (int nd2 = 0; nd2 < 4; nd2++) {
                int colblk = nd2 * 2 + vc_hi;
                unsigned addr = sVu +
                    (sbase + (unsigned)(row * 64 + ((colblk ^ (row & 7)) * 8))) * 2u;
                unsigned v0, v1, v2, v3;
                ldsm_x4_t(v0, v1, v2, v3, addr);
                { unsigned b2[2] = {v0, v1}; mma16816(o[2 * nd2], a, b2); }
                { unsigned b2[2] = {v2, v3}; mma16816(o[2 * nd2 + 1], a, b2); }
            }
        }
        if (++buf >= 3) buf = 0;
    }

    float inv0 = 1.f / l0, inv1 = 1.f / l1;
    float* Op0 = out + ((size_t)bidx * SS_ + qr) * DD_ + h * HDIM;
    float* Op1 = Op0 + 8 * DD_;
#pragma unroll
    for (int nd = 0; nd < 8; nd++) {
        int d = nd * 8 + 2 * t;
        *(float2*)(Op0 + d) = make_float2(o[nd][0] * inv0, o[nd][1] * inv0);
        *(float2*)(Op1 + d) = make_float2(o[nd][2] * inv1, o[nd][3] * inv1);
    }
}

// ---------------------------------------------------------------------------
extern "C" void kernel_launch(void* const* d_in, const int* in_sizes, int n_in,
                              void* d_out, int out_size) {
    (void)in_sizes; (void)n_in; (void)out_size;
    const float* query = (const float*)d_in[0];
    const float* key   = (const float*)d_in[1];
    const float* value = (const float*)d_in[2];
    const int*   mask  = (const int*)d_in[3];
    const float* Wq = (const float*)d_in[4];
    const float* bq = (const float*)d_in[5];
    const float* Wk = (const float*)d_in[6];
    const float* bk = (const float*)d_in[7];
    const float* Wv = (const float*)d_in[8];
    const float* bv = (const float*)d_in[9];

    prep_kernel<<<PREP_BLKS, 256>>>((const int4*)mask,
                                    (const float4*)query, (const float4*)key,
                                    (const float4*)value,
                                    (const float4*)Wq, (const float4*)Wk,
                                    (const float4*)Wv);

    const int proj_smem = 3 * (PSTG_A + PSTG_B) * (int)sizeof(__half);  // 73728 B
    cudaFuncSetAttribute(proj_kernel, cudaFuncAttributeMaxDynamicSharedMemorySize,
                         proj_smem);
    dim3 gp(DD_ / 64, (BB_ * SS_) / 128, 3);   // (16, 32, 3)
    proj_kernel<<<gp, 128, proj_smem>>>(bq, bk, bv);

    const int attn_smem = 6 * ASTG_H * (int)sizeof(__half);  // 49152 B
    cudaFuncSetAttribute(attn_kernel, cudaFuncAttributeMaxDynamicSharedMemorySize,
                         attn_smem);
    dim3 ga(SS_ / 64, BB_ * HH_);    // (32, 32)
    attn_kernel<<<ga, 128, attn_smem>>>((float*)d_out);
}